// round 9
// baseline (speedup 1.0000x reference)
#include <cuda_runtime.h>
#include <cuda_bf16.h>
#include <cstdint>

// ---------------------------------------------------------------------------
// KTBCrossAttention — persistent fused edition.
//   fused kernel (grid = 2*SMs, 128 thr, 96KB smem), phases:
//     P0   : zero Gf32 + pack X (bf16 hi/lo fragment layout) + pack Wk + pack Wv
//     P1   : G = XᵀX, split-K=4, 3xBF16 m16n8k16, partials atomicAdd -> Gf32
//     P1.5 : pack Gf32 (triangular source, symmetric) -> bf16 hi/lo fragments
//     P2   : U = WkᵀG (3xBF16) -> f32 row-major
//   ctx kernel: L_h = s*U_h@Wv_h via bf16x3 mma (split-in-reg A, packed Wv B),
//               column softmax -> ctx
//   out kernel: out = X @ blockdiag(ctx_other)  [tf32 mma]
//
// Pack layout for M[R][K] as bf16 pairs (uint32 = 2 adjacent k):
//   block = (r>>4)*(K>>4) + (k>>4); within: lane=(r&7)*4+((k>>1)&3),
//   reg=((r>>3)&1)+2*((k>>3)&1). One LDS/LDG.128 per lane = m16n8k16 A-frag;
//   as B operand the two 8-col halves use regs {x,z} / {y,w}.
// ---------------------------------------------------------------------------

#define DIMC 768
#define NTOK 4096
#define BATCH 16
#define NHEADS 12
#define HD 64

#define STAGES 3
#define STAGE_BYTES 32768                    // k32 slab: 4 quarters x 8KB
#define GEMM_SMEM (STAGES * STAGE_BYTES)     // 96 KB
#define OUT_SMEM ((128 * 68 + 64 * 68) * 4)  // 52.2 KB

#define XPB ((long long)DIMC * (NTOK / 2))   // per-z packed X u32
#define WPB ((long long)DIMC * (DIMC / 2))   // per-modality packed W u32
#define GPB ((long long)DIMC * (DIMC / 2))   // per-z packed G u32
#define UB  ((long long)DIMC * DIMC)         // per-z U f32
#define GFB ((long long)DIMC * DIMC)         // per-z Gf32

// scratch (device globals; allocation-free contract)
__device__ uint32_t g_Xh[2][BATCH][DIMC * (NTOK / 2)];
__device__ uint32_t g_Xl[2][BATCH][DIMC * (NTOK / 2)];
__device__ uint32_t g_Wh[2][DIMC * (DIMC / 2)];
__device__ uint32_t g_Wl[2][DIMC * (DIMC / 2)];
__device__ uint32_t g_Wvh[2][DIMC * (DIMC / 2)];
__device__ uint32_t g_Wvl[2][DIMC * (DIMC / 2)];
__device__ float    g_Gf[2][BATCH][DIMC * DIMC];       // f32 split-K accumulator
__device__ uint32_t g_Gh[2][BATCH][DIMC * (DIMC / 2)];
__device__ uint32_t g_Gl[2][BATCH][DIMC * (DIMC / 2)];
__device__ float    g_U[2][BATCH][DIMC * DIMC];
__device__ float    g_ctx[2][BATCH][NHEADS][HD * HD];

// grid-wide barrier state (self-resetting; generation is monotone across replays)
__device__ volatile unsigned g_bar_gen;
__device__ unsigned g_bar_cnt;

// ---------------------------------------------------------------------------
__device__ __forceinline__ uint32_t smem_to_u32(const void* p) {
    uint32_t a;
    asm("{ .reg .u64 tmp; cvta.to.shared.u64 tmp, %1; cvt.u32.u64 %0, tmp; }"
        : "=r"(a) : "l"(p));
    return a;
}

__device__ __forceinline__ void cp16(uint32_t saddr, const void* g) {
    asm volatile("cp.async.cg.shared.global [%0], [%1], 16;" :: "r"(saddr), "l"(g));
}
#define CP_COMMIT() asm volatile("cp.async.commit_group;" ::: "memory")
#define CP_WAIT(n)  asm volatile("cp.async.wait_group %0;" :: "n"(n) : "memory")

__device__ __forceinline__ uint4 lds128(uint32_t a) {
    uint4 v;
    asm volatile("ld.shared.v4.b32 {%0,%1,%2,%3}, [%4];"
                 : "=r"(v.x), "=r"(v.y), "=r"(v.z), "=r"(v.w) : "r"(a));
    return v;
}

__device__ __forceinline__ void mma_bf16(float* d, const uint32_t* a, const uint32_t* b) {
    asm volatile(
        "mma.sync.aligned.m16n8k16.row.col.f32.bf16.bf16.f32 "
        "{%0,%1,%2,%3}, {%4,%5,%6,%7}, {%8,%9}, {%0,%1,%2,%3};"
        : "+f"(d[0]), "+f"(d[1]), "+f"(d[2]), "+f"(d[3])
        : "r"(a[0]), "r"(a[1]), "r"(a[2]), "r"(a[3]), "r"(b[0]), "r"(b[1]));
}

__device__ __forceinline__ void mma_tf32(float* d, const uint32_t* a, const uint32_t* b) {
    asm volatile(
        "mma.sync.aligned.m16n8k8.row.col.f32.tf32.tf32.f32 "
        "{%0,%1,%2,%3}, {%4,%5,%6,%7}, {%8,%9}, {%0,%1,%2,%3};"
        : "+f"(d[0]), "+f"(d[1]), "+f"(d[2]), "+f"(d[3])
        : "r"(a[0]), "r"(a[1]), "r"(a[2]), "r"(a[3]), "r"(b[0]), "r"(b[1]));
}

__device__ __forceinline__ uint32_t to_tf32(float v) {
    uint32_t t;
    asm("cvt.rna.tf32.f32 %0, %1;" : "=r"(t) : "f"(v));
    return t;
}

__device__ __forceinline__ void split2_bf16(float a, float b,
                                            uint32_t& h, uint32_t& l) {
    __nv_bfloat16 ha = __float2bfloat16_rn(a);
    __nv_bfloat16 hb = __float2bfloat16_rn(b);
    float ra = a - __bfloat162float(ha);
    float rb = b - __bfloat162float(hb);
    __nv_bfloat16 la = __float2bfloat16_rn(ra);
    __nv_bfloat16 lb = __float2bfloat16_rn(rb);
    __nv_bfloat162 hp; hp.x = ha; hp.y = hb;
    __nv_bfloat162 lp; lp.x = la; lp.y = lb;
    h = *reinterpret_cast<uint32_t*>(&hp);
    l = *reinterpret_cast<uint32_t*>(&lp);
}

// ---------------------------------------------------------------------------
// Grid-wide barrier (all CTAs resident by construction).
// ---------------------------------------------------------------------------
__device__ __forceinline__ void grid_bar(int nCta) {
    __syncthreads();
    if (threadIdx.x == 0) {
        unsigned my = g_bar_gen;
        __threadfence();
        if (atomicAdd(&g_bar_cnt, 1) == (unsigned)(nCta - 1)) {
            g_bar_cnt = 0;
            __threadfence();
            g_bar_gen = my + 1;
        } else {
            while (g_bar_gen == my) { __nanosleep(64); }
            __threadfence();
        }
    }
    __syncthreads();
}

// ---------------------------------------------------------------------------
// Pack one 64r x 64k tile: src[k][r] (row stride srcLd) -> bf16 hi/lo
// fragment-packed arrays. 128 threads.
// ---------------------------------------------------------------------------
__device__ void pack_unit(const float* __restrict__ src, int srcLd, int Kb16,
                          uint32_t* __restrict__ oH, uint32_t* __restrict__ oL,
                          int r0, int k0, char* smem)
{
    float (*t)[65] = (float(*)[65])smem;
    const int tid = threadIdx.x;
#pragma unroll
    for (int it = 0; it < 32; it++) {
        const int row = it * 2 + (tid >> 6);
        const int col = tid & 63;
        t[row][col] = src[(long long)(k0 + row) * srcLd + r0 + col];
    }
    __syncthreads();
#pragma unroll
    for (int it = 0; it < 16; it++) {
        const int e = it * 128 + tid;
        const int w = e & 127;
        const int blk = e >> 7;
        const int mb = blk >> 2, kb = blk & 3;
        const int lane = w >> 2, reg = w & 3;
        const int rr = mb * 16 + (lane >> 2) + 8 * (reg & 1);
        const int kk = kb * 16 + ((lane & 3) + 4 * ((reg >> 1) & 1)) * 2;
        uint32_t h, l;
        split2_bf16(t[kk][rr], t[kk + 1][rr], h, l);
        const long long gi =
            (long long)(((r0 >> 4) + mb) * Kb16 + (k0 >> 4) + kb) * 128 + w;
        oH[gi] = h;
        oL[gi] = l;
    }
    __syncthreads();
}

// ---------------------------------------------------------------------------
// Pack one 64x64 tile of symmetric Gf32 (only upper triangle valid) into
// bf16 hi/lo fragments. Loads the upper-triangular mirror coalesced.
// ---------------------------------------------------------------------------
__device__ void packG_unit(const float* __restrict__ Gf,
                           uint32_t* __restrict__ oH, uint32_t* __restrict__ oL,
                           int r0, int k0, char* smem)
{
    float (*t)[65] = (float(*)[65])smem;
    const int tid = threadIdx.x;
    const int A0 = r0 < k0 ? r0 : k0;
    const int B0 = r0 < k0 ? k0 : r0;
#pragma unroll
    for (int it = 0; it < 32; it++) {
        const int row = it * 2 + (tid >> 6);
        const int col = tid & 63;
        t[row][col] = Gf[(long long)(A0 + row) * DIMC + B0 + col];
    }
    __syncthreads();
    const int swap = (r0 > k0);
    const int diag = (r0 == k0);
#pragma unroll
    for (int it = 0; it < 16; it++) {
        const int e = it * 128 + tid;
        const int w = e & 127;
        const int blk = e >> 7;
        const int mb = blk >> 2, kb = blk & 3;
        const int lane = w >> 2, reg = w & 3;
        const int rr = mb * 16 + (lane >> 2) + 8 * (reg & 1);
        const int kk = kb * 16 + ((lane & 3) + 4 * ((reg >> 1) & 1)) * 2;
        float v0, v1;
        if (diag) {
            v0 = (rr <= kk)     ? t[rr][kk]     : t[kk][rr];
            v1 = (rr <= kk + 1) ? t[rr][kk + 1] : t[kk + 1][rr];
        } else if (swap) {
            v0 = t[kk][rr];
            v1 = t[kk + 1][rr];
        } else {
            v0 = t[rr][kk];
            v1 = t[rr][kk + 1];
        }
        uint32_t h, l;
        split2_bf16(v0, v1, h, l);
        const long long gi =
            (long long)(((r0 >> 4) + mb) * 48 + (k0 >> 4) + kb) * 128 + w;
        oH[gi] = h;
        oL[gi] = l;
    }
    __syncthreads();
}

// ---------------------------------------------------------------------------
// One 128x128 GEMM unit over nSlab k32 slabs starting at kblock kOff16.
// mode 0: atomicAdd partials into f32 row-major (Gf); mode 1: store f32 (U).
// ---------------------------------------------------------------------------
__device__ void gemm_unit(
    const uint32_t* __restrict__ Ah, const uint32_t* __restrict__ Al,
    const uint32_t* __restrict__ Bh, const uint32_t* __restrict__ Bl,
    int Kb16, int kOff16, int nSlab,
    int ci0, int cj0,
    float* __restrict__ outF, int mode,
    char* smem)
{
    const uint32_t smem_base = smem_to_u32(smem);
    const int tid = threadIdx.x;
    const int wid = tid >> 5, lane = tid & 31;
    const int wm = wid >> 1, wnn = wid & 1;
    const int grp = lane >> 2, qid = lane & 3;

    const uint32_t* gq = (wid == 0) ? Ah : (wid == 1) ? Al : (wid == 2) ? Bh : Bl;
    const int rowblk0 = ((wid < 2) ? ci0 : cj0) >> 4;
    const uint32_t* gsrc = gq + ((long long)rowblk0 * Kb16 + kOff16) * 128 + lane * 4;
    const uint32_t sdst0 = smem_base + wid * 8192 + lane * 16;

    float acc[4][8][4];
#pragma unroll
    for (int a = 0; a < 4; a++)
#pragma unroll
        for (int b = 0; b < 8; b++)
#pragma unroll
            for (int c = 0; c < 4; c++) acc[a][b][c] = 0.f;

#pragma unroll
    for (int s = 0; s < STAGES - 1; s++) {
        const uint32_t d = sdst0 + s * STAGE_BYTES;
#pragma unroll
        for (int mb = 0; mb < 8; mb++)
#pragma unroll
            for (int kb = 0; kb < 2; kb++)
                cp16(d + mb * 1024 + kb * 512,
                     gsrc + (long long)mb * Kb16 * 128 + (2 * s + kb) * 128);
        CP_COMMIT();
    }

    int sidx = 0, pidx = STAGES - 1;
    for (int s = 0; s < nSlab; s++) {
        if (s + STAGES - 1 < nSlab) {
            const int sp = s + STAGES - 1;
            const uint32_t d = sdst0 + pidx * STAGE_BYTES;
#pragma unroll
            for (int mb = 0; mb < 8; mb++)
#pragma unroll
                for (int kb = 0; kb < 2; kb++)
                    cp16(d + mb * 1024 + kb * 512,
                         gsrc + (long long)mb * Kb16 * 128 + (2 * sp + kb) * 128);
        }
        CP_COMMIT();
        CP_WAIT(STAGES - 1);
        __syncthreads();

        const uint32_t st = smem_base + sidx * STAGE_BYTES;
#pragma unroll
        for (int kb = 0; kb < 2; kb++) {
            uint4 bhv[4], blv[4];
#pragma unroll
            for (int nb = 0; nb < 4; nb++) {
                const uint32_t ba = st + (wnn * 4 + nb) * 1024 + kb * 512 + lane * 16;
                bhv[nb] = lds128(ba + 16384);
                blv[nb] = lds128(ba + 24576);
            }
#pragma unroll
            for (int mi = 0; mi < 4; mi++) {
                const uint32_t aa = st + (wm * 4 + mi) * 1024 + kb * 512 + lane * 16;
                uint4 ah = lds128(aa);
                uint4 al = lds128(aa + 8192);
#pragma unroll
                for (int nb = 0; nb < 4; nb++) {
                    uint32_t bh0[2] = {bhv[nb].x, bhv[nb].z};
                    uint32_t bl0[2] = {blv[nb].x, blv[nb].z};
                    uint32_t bh1[2] = {bhv[nb].y, bhv[nb].w};
                    uint32_t bl1[2] = {blv[nb].y, blv[nb].w};
                    float* a0 = acc[mi][nb * 2];
                    float* a1 = acc[mi][nb * 2 + 1];
                    mma_bf16(a0, (const uint32_t*)&ah, bh0);
                    mma_bf16(a0, (const uint32_t*)&al, bh0);
                    mma_bf16(a0, (const uint32_t*)&ah, bl0);
                    mma_bf16(a1, (const uint32_t*)&ah, bh1);
                    mma_bf16(a1, (const uint32_t*)&al, bh1);
                    mma_bf16(a1, (const uint32_t*)&ah, bl1);
                }
            }
        }
        __syncthreads();
        if (++sidx == STAGES) sidx = 0;
        if (++pidx == STAGES) pidx = 0;
    }

#pragma unroll
    for (int mi = 0; mi < 4; mi++) {
        const int r = ci0 + wm * 64 + mi * 16 + grp;
#pragma unroll
        for (int nj = 0; nj < 8; nj++) {
            const int c = cj0 + wnn * 64 + (nj >> 1) * 16 + (nj & 1) * 8 + 2 * qid;
            if (mode == 0) {
                atomicAdd(&outF[(long long)r * DIMC + c],       acc[mi][nj][0]);
                atomicAdd(&outF[(long long)r * DIMC + c + 1],   acc[mi][nj][1]);
                atomicAdd(&outF[(long long)(r + 8) * DIMC + c],     acc[mi][nj][2]);
                atomicAdd(&outF[(long long)(r + 8) * DIMC + c + 1], acc[mi][nj][3]);
            } else {
                *(float2*)&outF[(long long)r * DIMC + c] =
                    make_float2(acc[mi][nj][0], acc[mi][nj][1]);
                *(float2*)&outF[(long long)(r + 8) * DIMC + c] =
                    make_float2(acc[mi][nj][2], acc[mi][nj][3]);
            }
        }
    }
}

// ---------------------------------------------------------------------------
// Persistent fused kernel: P0 zero+pack / P1 G split-K / P1.5 packG / P2 U
// ---------------------------------------------------------------------------
__global__ __launch_bounds__(128, 2) void fused_kernel(
    const float* __restrict__ rgb, const float* __restrict__ dep,
    const float* __restrict__ Wr, const float* __restrict__ Wd,
    int nCta)
{
    extern __shared__ char smem[];
    const int tid = threadIdx.x;
    const int cta = blockIdx.x;

    uint32_t* Xh = &g_Xh[0][0][0];
    uint32_t* Xl = &g_Xl[0][0][0];
    uint32_t* Wh = &g_Wh[0][0];
    uint32_t* Wl = &g_Wl[0][0];
    uint32_t* Wvh = &g_Wvh[0][0];
    uint32_t* Wvl = &g_Wvl[0][0];
    float*    Gf = &g_Gf[0][0][0];
    uint32_t* Gh = &g_Gh[0][0][0];
    uint32_t* Gl = &g_Gl[0][0][0];
    float*    U  = &g_U[0][0][0];

    // ---- P0: zero Gf32 ----
    {
        const long long NZ4 = (2LL * BATCH * DIMC * DIMC) >> 2;  // uint4 count
        uint4 z4 = make_uint4(0, 0, 0, 0);
        uint4* pZ = (uint4*)Gf;
        for (long long i = (long long)cta * 128 + tid; i < NZ4;
             i += (long long)nCta * 128)
            pZ[i] = z4;
    }
    // ---- P0: pack X (24576 units) ----
    for (int u = cta; u < 24576; u += nCta) {
        const int z = u / 768, rem = u % 768;
        const int rx = rem / 64, ky = rem % 64;
        const float* src = (z < 16)
            ? rgb + (long long)z * NTOK * DIMC
            : dep + (long long)(z - 16) * NTOK * DIMC;
        pack_unit(src, DIMC, NTOK / 16, Xh + z * XPB, Xl + z * XPB,
                  rx * 64, ky * 64, smem);
    }
    // ---- P0: pack Wk + Wv (576 units) ----
    for (int u = cta; u < 576; u += nCta) {
        const int m = u / 288, rem = u % 288;
        const int part = rem / 144, rem2 = rem % 144;
        const int rx = rem2 / 12, ky = rem2 % 12;
        const float* src = (m ? Wd : Wr) + (part ? DIMC : 0);
        uint32_t* dh = part ? (Wvh + m * WPB) : (Wh + m * WPB);
        uint32_t* dl = part ? (Wvl + m * WPB) : (Wl + m * WPB);
        pack_unit(src, 2 * DIMC, 48, dh, dl, rx * 64, ky * 64, smem);
    }
    grid_bar(nCta);

    // ---- P1: G = XᵀX, split-K=4 (2688 units) ----
    for (int u = cta; u < 2688; u += nCta) {
        const int ks = u & 3;
        const int tz = u >> 2;
        const int z = tz / 21;
        int rem = tz % 21, ti = 0;
        while (rem >= 6 - ti) { rem -= (6 - ti); ti++; }
        const int tj = ti + rem;
        const uint32_t* ah = Xh + z * XPB;
        const uint32_t* al = Xl + z * XPB;
        gemm_unit(ah, al, ah, al, NTOK / 16, ks * 64, 32,
                  ti * 128, tj * 128, Gf + z * GFB, 0, smem);
    }
    grid_bar(nCta);

    // ---- P1.5: pack G (4608 units) ----
    for (int u = cta; u < 4608; u += nCta) {
        const int z = u / 144, rem = u % 144;
        const int rx = rem / 12, ky = rem % 12;
        packG_unit(Gf + z * GFB, Gh + z * GPB, Gl + z * GPB,
                   rx * 64, ky * 64, smem);
    }
    grid_bar(nCta);

    // ---- P2: U = WkᵀG (1152 units) ----
    for (int u = cta; u < 1152; u += nCta) {
        const int z = u / 36, tile = u % 36;
        const int ti = tile / 6, tj = tile % 6;
        const int m = z >> 4;
        gemm_unit(Wh + m * WPB, Wl + m * WPB, Gh + z * GPB, Gl + z * GPB,
                  48, 0, 24, ti * 128, tj * 128, U + z * UB, 1, smem);
    }
}

// ---------------------------------------------------------------------------
// ctx: L[d][e] = s * sum_c U[h*64+d][c] * Wv[c][h*64+e]  via bf16x3 mma,
// then column-wise softmax (over d) -> g_ctx. grid (12, 32), block 256.
// ---------------------------------------------------------------------------
__global__ __launch_bounds__(256) void ctx_kernel()
{
    __shared__ float Ls[64][68];
    const int z = blockIdx.y;
    const int m = z >> 4, b = z & 15;
    const int h = blockIdx.x;
    const float* U = &g_U[m][b][0] + (long long)(h * 64) * DIMC;
    const uint32_t* Bh = &g_Wvh[m][0];
    const uint32_t* Bl = &g_Wvl[m][0];

    const int tid = threadIdx.x;
    const int wid = tid >> 5, lane = tid & 31;
    const int wm = wid >> 1, wn = wid & 1;
    const int grp = lane >> 2, qid = lane & 3;

    float acc[2][2][4];
#pragma unroll
    for (int a = 0; a < 2; a++)
#pragma unroll
        for (int c = 0; c < 2; c++)
#pragma unroll
            for (int r = 0; r < 4; r++) acc[a][c][r] = 0.f;

    for (int ks = 0; ks < 48; ks++) {
        const float* Ur = U + (long long)(wm * 16 + grp) * DIMC + ks * 16 + 2 * qid;
        float2 p0 = *(const float2*)(Ur);
        float2 p1 = *(const float2*)(Ur + 8 * DIMC);
        float2 p2 = *(const float2*)(Ur + 8);
        float2 p3 = *(const float2*)(Ur + 8 * DIMC + 8);
        uint32_t ah[4], al[4];
        split2_bf16(p0.x, p0.y, ah[0], al[0]);
        split2_bf16(p1.x, p1.y, ah[1], al[1]);
        split2_bf16(p2.x, p2.y, ah[2], al[2]);
        split2_bf16(p3.x, p3.y, ah[3], al[3]);
#pragma unroll
        for (int nb = 0; nb < 2; nb++) {
            const long long gi =
                ((long long)(4 * h + 2 * wn + nb) * 48 + ks) * 128 + lane * 4;
            uint4 bh = *(const uint4*)(Bh + gi);
            uint4 bl = *(const uint4*)(Bl + gi);
            uint32_t bh0[2] = {bh.x, bh.z};
            uint32_t bl0[2] = {bl.x, bl.z};
            uint32_t bh1[2] = {bh.y, bh.w};
            uint32_t bl1[2] = {bl.y, bl.w};
            mma_bf16(acc[nb][0], ah, bh0);
            mma_bf16(acc[nb][0], al, bh0);
            mma_bf16(acc[nb][0], ah, bl0);
            mma_bf16(acc[nb][1], ah, bh1);
            mma_bf16(acc[nb][1], al, bh1);
            mma_bf16(acc[nb][1], ah, bl1);
        }
    }

    const float SCALE = 0.125f;
#pragma unroll
    for (int nb = 0; nb < 2; nb++)
#pragma unroll
        for (int hf = 0; hf < 2; hf++) {
            const int r = wm * 16 + grp;
            const int c = wn * 32 + nb * 16 + hf * 8 + 2 * qid;
            Ls[r][c]         = acc[nb][hf][0] * SCALE;
            Ls[r][c + 1]     = acc[nb][hf][1] * SCALE;
            Ls[r + 8][c]     = acc[nb][hf][2] * SCALE;
            Ls[r + 8][c + 1] = acc[nb][hf][3] * SCALE;
        }
    __syncthreads();

    if (tid < 64) {
        const int e = tid;
        float mx = -1e30f;
#pragma unroll 8
        for (int d = 0; d < 64; d++) mx = fmaxf(mx, Ls[d][e]);
        float s = 0.f;
#pragma unroll 8
        for (int d = 0; d < 64; d++) {
            float v = expf(Ls[d][e] - mx);
            Ls[d][e] = v;
            s += v;
        }
        const float inv = 1.f / s;
        float* cx = &g_ctx[m][b][h][0];
#pragma unroll 8
        for (int d = 0; d < 64; d++) cx[d * 64 + e] = Ls[d][e] * inv;
    }
}

// ---------------------------------------------------------------------------
// out_m[b, n, h*64+e] = sum_d X_m[b, n, h*64+d] * ctx_{1-m}[b][h][d][e]
// ---------------------------------------------------------------------------
__global__ __launch_bounds__(256) void out_kernel(
    const float* __restrict__ rgb, const float* __restrict__ depth,
    float* __restrict__ out)
{
    extern __shared__ char smem[];
    uint32_t* As = (uint32_t*)smem;                 // [128][68]
    uint32_t* Bs = (uint32_t*)smem + 128 * 68;      // [64][68]

    const int z = blockIdx.z;
    const int m = z >> 4, b = z & 15;
    const int h = blockIdx.y;
    const int n0 = blockIdx.x * 128;

    const float* X = (m == 0 ? rgb : depth) + ((long long)b * NTOK + n0) * DIMC + h * HD;
    const float* cx = &g_ctx[1 - m][b][h][0];
    float* O = out + (long long)m * BATCH * NTOK * DIMC + ((long long)b * NTOK + n0) * DIMC + h * HD;

    const int tid = threadIdx.x;
    const int wid = tid >> 5, lane = tid & 31;
    const int wm = wid >> 2, wn = wid & 3;
    const int grp = lane >> 2, qid = lane & 3;

#pragma unroll
    for (int t = 0; t < 8; t++) {
        const int f4 = tid + t * 256;
        const int r = f4 >> 4;
        const int cg = (f4 & 15) << 2;
        float4 v = *(const float4*)(X + (long long)r * DIMC + cg);
        As[r * 68 + cg + 0] = to_tf32(v.x); As[r * 68 + cg + 1] = to_tf32(v.y);
        As[r * 68 + cg + 2] = to_tf32(v.z); As[r * 68 + cg + 3] = to_tf32(v.w);
    }
#pragma unroll
    for (int t = 0; t < 4; t++) {
        const int f4 = tid + t * 256;
        const int d = f4 >> 4;
        const int eg = (f4 & 15) << 2;
        float4 v = *(const float4*)(cx + d * 64 + eg);
        Bs[(eg + 0) * 68 + d] = to_tf32(v.x); Bs[(eg + 1) * 68 + d] = to_tf32(v.y);
        Bs[(eg + 2) * 68 + d] = to_tf32(v.z); Bs[(eg + 3) * 68 + d] = to_tf32(v.w);
    }
    __syncthreads();

    float acc[4][2][4];
#pragma unroll
    for (int a = 0; a < 4; a++)
#pragma unroll
        for (int c = 0; c < 2; c++)
#pragma unroll
            for (int r = 0; r < 4; r++) acc[a][c][r] = 0.f;

#pragma unroll
    for (int ks = 0; ks < 8; ks++) {
        const int kq = (ks << 3) + qid;
        uint32_t ah[4][4], bh[2][2];
#pragma unroll
        for (int mi = 0; mi < 4; mi++) {
            const int i = wm * 64 + mi * 16 + grp;
            ah[mi][0] = As[i * 68 + kq];           ah[mi][1] = As[(i + 8) * 68 + kq];
            ah[mi][2] = As[i * 68 + kq + 4];       ah[mi][3] = As[(i + 8) * 68 + kq + 4];
        }
#pragma unroll
        for (int nj = 0; nj < 2; nj++) {
            const int n = wn * 16 + nj * 8 + grp;
            bh[nj][0] = Bs[n * 68 + kq]; bh[nj][1] = Bs[n * 68 + kq + 4];
        }
#pragma unroll
        for (int mi = 0; mi < 4; mi++)
#pragma unroll
            for (int nj = 0; nj < 2; nj++)
                mma_tf32(acc[mi][nj], ah[mi], bh[nj]);
    }

#pragma unroll
    for (int mi = 0; mi < 4; mi++) {
        const int r0 = wm * 64 + mi * 16 + grp;
#pragma unroll
        for (int nj = 0; nj < 2; nj++) {
            const int c0c = wn * 16 + nj * 8 + 2 * qid;
            *(float2*)(O + (long long)r0 * DIMC + c0c) =
                make_float2(acc[mi][nj][0], acc[mi][nj][1]);
            *(float2*)(O + (long long)(r0 + 8) * DIMC + c0c) =
                make_float2(acc[mi][nj][2], acc[mi][nj][3]);
        }
    }
}

// ---------------------------------------------------------------------------
extern "C" void kernel_launch(void* const* d_in, const int* in_sizes, int n_in,
                              void* d_out, int out_size)
{
    const float* rgb = (const float*)d_in[0];
    const float* dep = (const float*)d_in[1];
    const float* Wr  = (const float*)d_in[2];
    const float* Wd  = (const float*)d_in[3];
    float* out = (float*)d_out;

    int nsm = 148;
    cudaDeviceGetAttribute(&nsm, cudaDevAttrMultiProcessorCount, 0);
    const int nCta = nsm * 2;

    cudaFuncSetAttribute(fused_kernel,
                         cudaFuncAttributeMaxDynamicSharedMemorySize, GEMM_SMEM);
    cudaFuncSetAttribute(out_kernel,
                         cudaFuncAttributeMaxDynamicSharedMemorySize, OUT_SMEM);

    // persistent fused: zero + pack + G(split-K) + packG + U
    fused_kernel<<<nCta, 128, GEMM_SMEM>>>(rgb, dep, Wr, Wd, nCta);

    // per-head logits (bf16x3 mma) + softmax -> ctx
    ctx_kernel<<<dim3(NHEADS, 32), 256>>>();

    // out = X @ blockdiag(ctx_other), 128-row tiles
    out_kernel<<<dim3(NTOK / 128, NHEADS, 32), 256, OUT_SMEM>>>(rgb, dep, out);
}

// round 11
// speedup vs baseline: 1.1249x; 1.1249x over previous
#include <cuda_runtime.h>
#include <cuda_bf16.h>
#include <cstdint>

// ---------------------------------------------------------------------------
// KTBCrossAttention (R11 = R10 re-bench): R8 structure + no-atomic split-K G
// + bf16-mma ctx.
//   pack X/Wk/Wv -> bf16 hi/lo fragment arrays
//   G = XᵀX: split-K=2, each half stores f32 plane (triangular tiles only)
//   packG: plane0+plane1, symmetric expansion, bf16 hi/lo fragment pack
//   U = WkᵀG (3xBF16) -> f32 row-major
//   ctx: L = s*U_h@Wv_h via bf16x3 mma, column softmax
//   out = X @ blockdiag(ctx_other)  [tf32 mma]
//
// Pack layout for M[R][K] as bf16 pairs (uint32 = 2 adjacent k):
//   block = (r>>4)*(K>>4) + (k>>4); within: lane=(r&7)*4+((k>>1)&3),
//   reg=((r>>3)&1)+2*((k>>3)&1). One LDS/LDG.128 per lane = m16n8k16 A-frag;
//   as B operand the two 8-col halves use regs {x,z} / {y,w}.
// ---------------------------------------------------------------------------

#define DIMC 768
#define NTOK 4096
#define BATCH 16
#define NHEADS 12
#define HD 64

#define STAGES 3
#define STAGE_BYTES 32768                    // k32 slab: 4 quarters x 8KB
#define GEMM_SMEM (STAGES * STAGE_BYTES)     // 96 KB
#define OUT_SMEM ((128 * 68 + 64 * 68) * 4)  // 52.2 KB

#define XPB ((long long)DIMC * (NTOK / 2))
#define WPB ((long long)DIMC * (DIMC / 2))
#define GPB ((long long)DIMC * (DIMC / 2))
#define UBE ((long long)DIMC * DIMC)
#define GFB ((long long)DIMC * DIMC)

// scratch (device globals; allocation-free contract)
__device__ uint32_t g_Xh[2][BATCH][DIMC * (NTOK / 2)];
__device__ uint32_t g_Xl[2][BATCH][DIMC * (NTOK / 2)];
__device__ uint32_t g_Wh[2][DIMC * (DIMC / 2)];
__device__ uint32_t g_Wl[2][DIMC * (DIMC / 2)];
__device__ uint32_t g_Wvh[2][DIMC * (DIMC / 2)];
__device__ uint32_t g_Wvl[2][DIMC * (DIMC / 2)];
__device__ float    g_Gf[2][2][BATCH][DIMC * DIMC];    // [plane][m][b] f32 partials
__device__ uint32_t g_Gh[2][BATCH][DIMC * (DIMC / 2)];
__device__ uint32_t g_Gl[2][BATCH][DIMC * (DIMC / 2)];
__device__ float    g_U[2][BATCH][DIMC * DIMC];
__device__ float    g_ctx[2][BATCH][NHEADS][HD * HD];

// ---------------------------------------------------------------------------
__device__ __forceinline__ uint32_t smem_to_u32(const void* p) {
    uint32_t a;
    asm("{ .reg .u64 tmp; cvta.to.shared.u64 tmp, %1; cvt.u32.u64 %0, tmp; }"
        : "=r"(a) : "l"(p));
    return a;
}

__device__ __forceinline__ void cp16(uint32_t saddr, const void* g) {
    asm volatile("cp.async.cg.shared.global [%0], [%1], 16;" :: "r"(saddr), "l"(g));
}
#define CP_COMMIT() asm volatile("cp.async.commit_group;" ::: "memory")
#define CP_WAIT(n)  asm volatile("cp.async.wait_group %0;" :: "n"(n) : "memory")

__device__ __forceinline__ uint4 lds128(uint32_t a) {
    uint4 v;
    asm volatile("ld.shared.v4.b32 {%0,%1,%2,%3}, [%4];"
                 : "=r"(v.x), "=r"(v.y), "=r"(v.z), "=r"(v.w) : "r"(a));
    return v;
}

__device__ __forceinline__ void mma_bf16(float* d, const uint32_t* a, const uint32_t* b) {
    asm volatile(
        "mma.sync.aligned.m16n8k16.row.col.f32.bf16.bf16.f32 "
        "{%0,%1,%2,%3}, {%4,%5,%6,%7}, {%8,%9}, {%0,%1,%2,%3};"
        : "+f"(d[0]), "+f"(d[1]), "+f"(d[2]), "+f"(d[3])
        : "r"(a[0]), "r"(a[1]), "r"(a[2]), "r"(a[3]), "r"(b[0]), "r"(b[1]));
}

__device__ __forceinline__ void mma_tf32(float* d, const uint32_t* a, const uint32_t* b) {
    asm volatile(
        "mma.sync.aligned.m16n8k8.row.col.f32.tf32.tf32.f32 "
        "{%0,%1,%2,%3}, {%4,%5,%6,%7}, {%8,%9}, {%0,%1,%2,%3};"
        : "+f"(d[0]), "+f"(d[1]), "+f"(d[2]), "+f"(d[3])
        : "r"(a[0]), "r"(a[1]), "r"(a[2]), "r"(a[3]), "r"(b[0]), "r"(b[1]));
}

__device__ __forceinline__ uint32_t to_tf32(float v) {
    uint32_t t;
    asm("cvt.rna.tf32.f32 %0, %1;" : "=r"(t) : "f"(v));
    return t;
}

__device__ __forceinline__ void split2_bf16(float a, float b,
                                            uint32_t& h, uint32_t& l) {
    __nv_bfloat16 ha = __float2bfloat16_rn(a);
    __nv_bfloat16 hb = __float2bfloat16_rn(b);
    float ra = a - __bfloat162float(ha);
    float rb = b - __bfloat162float(hb);
    __nv_bfloat16 la = __float2bfloat16_rn(ra);
    __nv_bfloat16 lb = __float2bfloat16_rn(rb);
    __nv_bfloat162 hp; hp.x = ha; hp.y = hb;
    __nv_bfloat162 lp; lp.x = la; lp.y = lb;
    h = *reinterpret_cast<uint32_t*>(&hp);
    l = *reinterpret_cast<uint32_t*>(&lp);
}

// ---------------------------------------------------------------------------
// Pre-pass: read src[k][r] (row stride srcLd), transpose via smem, bf16-split,
// write fragment-packed hi/lo arrays. Tile = 64r x 64k.
// ---------------------------------------------------------------------------
__global__ __launch_bounds__(256) void pack_bf16_kernel(
    const float* __restrict__ srcA, const float* __restrict__ srcB,
    long long srcBStr, int srcLd, int K, int zdiv,
    uint32_t* __restrict__ oH, uint32_t* __restrict__ oL, long long dstBStr)
{
    __shared__ float t[64][65];
    const int z = blockIdx.z;
    const int m = z / zdiv, b = z % zdiv;
    const float* src = (m == 0 ? srcA : srcB) + (long long)b * srcBStr;
    oH += (long long)z * dstBStr;
    oL += (long long)z * dstBStr;

    const int r0 = blockIdx.x * 64, k0 = blockIdx.y * 64;
    const int tid = threadIdx.x;
    const int Kb16 = K >> 4;

#pragma unroll
    for (int it = 0; it < 16; it++) {
        const int row = it * 4 + (tid >> 6);
        const int col = tid & 63;
        t[row][col] = src[(long long)(k0 + row) * srcLd + r0 + col];
    }
    __syncthreads();

#pragma unroll
    for (int it = 0; it < 8; it++) {
        const int e = it * 256 + tid;
        const int w = e & 127;
        const int blk = e >> 7;
        const int mb = blk >> 2, kb = blk & 3;
        const int lane = w >> 2, reg = w & 3;
        const int rr = mb * 16 + (lane >> 2) + 8 * (reg & 1);
        const int kk = kb * 16 + ((lane & 3) + 4 * ((reg >> 1) & 1)) * 2;
        uint32_t h, l;
        split2_bf16(t[kk][rr], t[kk + 1][rr], h, l);
        const long long gidx =
            (long long)(((r0 >> 4) + mb) * Kb16 + (k0 >> 4) + kb) * 128 + w;
        oH[gidx] = h;
        oL[gidx] = l;
    }
}

// ---------------------------------------------------------------------------
// GEMM C[i][j] = sum_k A[i][k] B[j][k] over a k-range; f32 row-major store.
// 128x128 CTA tile, 2x2 warps of 64x64, k32 slabs, 3-stage cp.async, 3xBF16.
// blockIdx.x = tile * nSplit + ks; kOff16 = ks * nSlab * 2.
// sym=1: triangular tile set (G); sym=0: full 6x6 (U).
// out = oF + z*oBStr + ks*planeStr.
// ---------------------------------------------------------------------------
__global__ __launch_bounds__(128, 2) void gemm_bf16_kernel(
    const uint32_t* __restrict__ Ah, const uint32_t* __restrict__ Al,
    long long aBStr, int aDiv,
    const uint32_t* __restrict__ Bh, const uint32_t* __restrict__ Bl,
    long long bBStr,
    int Kb16, int nSlab, int nSplit, int sym,
    float* __restrict__ oF, long long oBStr, long long planeStr)
{
    extern __shared__ char smem[];
    const uint32_t smem_base = smem_to_u32(smem);
    const int tid = threadIdx.x;
    const int wid = tid >> 5, lane = tid & 31;
    const int wm = wid >> 1, wnn = wid & 1;
    const int grp = lane >> 2, qid = lane & 3;
    const int z = blockIdx.y;

    const int tile = blockIdx.x / nSplit;
    const int ks = blockIdx.x % nSplit;
    const int kOff16 = ks * nSlab * 2;

    const long long aOff = (long long)(z / aDiv) * aBStr;
    Ah += aOff; Al += aOff;
    Bh += z * bBStr; Bl += z * bBStr;
    float* out = oF + z * oBStr + ks * planeStr;

    int ti, tj;
    if (sym) {
        int rem = tile;
        ti = 0;
        while (rem >= 6 - ti) { rem -= (6 - ti); ti++; }
        tj = ti + rem;
    } else {
        ti = tile / 6;
        tj = tile % 6;
    }
    const int ci0 = ti * 128, cj0 = tj * 128;

    const uint32_t* gq = (wid == 0) ? Ah : (wid == 1) ? Al : (wid == 2) ? Bh : Bl;
    const int rowblk0 = ((wid < 2) ? ci0 : cj0) >> 4;
    const uint32_t* gsrc = gq + ((long long)rowblk0 * Kb16 + kOff16) * 128 + lane * 4;
    const uint32_t sdst0 = smem_base + wid * 8192 + lane * 16;

    float acc[4][8][4];
#pragma unroll
    for (int a = 0; a < 4; a++)
#pragma unroll
        for (int b = 0; b < 8; b++)
#pragma unroll
            for (int c = 0; c < 4; c++) acc[a][b][c] = 0.f;

#pragma unroll
    for (int s = 0; s < STAGES - 1; s++) {
        const uint32_t d = sdst0 + s * STAGE_BYTES;
#pragma unroll
        for (int mb = 0; mb < 8; mb++)
#pragma unroll
            for (int kb = 0; kb < 2; kb++)
                cp16(d + mb * 1024 + kb * 512,
                     gsrc + (long long)mb * Kb16 * 128 + (2 * s + kb) * 128);
        CP_COMMIT();
    }

    int sidx = 0, pidx = STAGES - 1;
    for (int s = 0; s < nSlab; s++) {
        if (s + STAGES - 1 < nSlab) {
            const int sp = s + STAGES - 1;
            const uint32_t d = sdst0 + pidx * STAGE_BYTES;
#pragma unroll
            for (int mb = 0; mb < 8; mb++)
#pragma unroll
                for (int kb = 0; kb < 2; kb++)
                    cp16(d + mb * 1024 + kb * 512,
                         gsrc + (long long)mb * Kb16 * 128 + (2 * sp + kb) * 128);
        }
        CP_COMMIT();
        CP_WAIT(STAGES - 1);
        __syncthreads();

        const uint32_t st = smem_base + sidx * STAGE_BYTES;
#pragma unroll
        for (int kb = 0; kb < 2; kb++) {
            uint4 bhv[4], blv[4];
#pragma unroll
            for (int nb = 0; nb < 4; nb++) {
                const uint32_t ba = st + (wnn * 4 + nb) * 1024 + kb * 512 + lane * 16;
                bhv[nb] = lds128(ba + 16384);
                blv[nb] = lds128(ba + 24576);
            }
#pragma unroll
            for (int mi = 0; mi < 4; mi++) {
                const uint32_t aa = st + (wm * 4 + mi) * 1024 + kb * 512 + lane * 16;
                uint4 ah = lds128(aa);
                uint4 al = lds128(aa + 8192);
#pragma unroll
                for (int nb = 0; nb < 4; nb++) {
                    uint32_t bh0[2] = {bhv[nb].x, bhv[nb].z};
                    uint32_t bl0[2] = {blv[nb].x, blv[nb].z};
                    uint32_t bh1[2] = {bhv[nb].y, bhv[nb].w};
                    uint32_t bl1[2] = {blv[nb].y, blv[nb].w};
                    float* a0 = acc[mi][nb * 2];
                    float* a1 = acc[mi][nb * 2 + 1];
                    mma_bf16(a0, (const uint32_t*)&ah, bh0);
                    mma_bf16(a0, (const uint32_t*)&al, bh0);
                    mma_bf16(a0, (const uint32_t*)&ah, bl0);
                    mma_bf16(a1, (const uint32_t*)&ah, bh1);
                    mma_bf16(a1, (const uint32_t*)&al, bh1);
                    mma_bf16(a1, (const uint32_t*)&ah, bl1);
                }
            }
        }
        __syncthreads();
        if (++sidx == STAGES) sidx = 0;
        if (++pidx == STAGES) pidx = 0;
    }

    // f32 row-major epilogue
#pragma unroll
    for (int mi = 0; mi < 4; mi++) {
        const int r = ci0 + wm * 64 + mi * 16 + grp;
#pragma unroll
        for (int nj = 0; nj < 8; nj++) {
            const int c = cj0 + wnn * 64 + (nj >> 1) * 16 + (nj & 1) * 8 + 2 * qid;
            *(float2*)&out[(long long)r * DIMC + c] =
                make_float2(acc[mi][nj][0], acc[mi][nj][1]);
            *(float2*)&out[(long long)(r + 8) * DIMC + c] =
                make_float2(acc[mi][nj][2], acc[mi][nj][3]);
        }
    }
}

// ---------------------------------------------------------------------------
// packG: sum two f32 planes (triangular tiles valid), symmetric expansion,
// bf16 hi/lo fragment pack. grid (144, 32), 128 threads; tile = 64x64.
// ---------------------------------------------------------------------------
__global__ __launch_bounds__(128) void packG_kernel()
{
    __shared__ float t[64][65];
    const int z = blockIdx.y;
    const int rem = blockIdx.x;
    const int r0 = (rem / 12) * 64, k0 = (rem % 12) * 64;
    const int tid = threadIdx.x;

    const float* p0 = &g_Gf[0][0][0][0] + (long long)z * GFB;
    const float* p1 = &g_Gf[1][0][0][0] + (long long)z * GFB;
    uint32_t* oH = &g_Gh[0][0][0] + (long long)z * GPB;
    uint32_t* oL = &g_Gl[0][0][0] + (long long)z * GPB;

    const int A0 = r0 < k0 ? r0 : k0;
    const int B0 = r0 < k0 ? k0 : r0;
#pragma unroll
    for (int it = 0; it < 32; it++) {
        const int row = it * 2 + (tid >> 6);
        const int col = tid & 63;
        const long long idx = (long long)(A0 + row) * DIMC + B0 + col;
        t[row][col] = p0[idx] + p1[idx];
    }
    __syncthreads();

    const int swap = (r0 > k0);
    const int diag = (r0 == k0);
#pragma unroll
    for (int it = 0; it < 16; it++) {
        const int e = it * 128 + tid;
        const int w = e & 127;
        const int blk = e >> 7;
        const int mb = blk >> 2, kb = blk & 3;
        const int lane = w >> 2, reg = w & 3;
        const int rr = mb * 16 + (lane >> 2) + 8 * (reg & 1);
        const int kk = kb * 16 + ((lane & 3) + 4 * ((reg >> 1) & 1)) * 2;
        float v0, v1;
        if (diag) {
            v0 = (rr <= kk)     ? t[rr][kk]     : t[kk][rr];
            v1 = (rr <= kk + 1) ? t[rr][kk + 1] : t[kk + 1][rr];
        } else if (swap) {
            v0 = t[kk][rr];
            v1 = t[kk + 1][rr];
        } else {
            v0 = t[rr][kk];
            v1 = t[rr][kk + 1];
        }
        uint32_t h, l;
        split2_bf16(v0, v1, h, l);
        const long long gi =
            (long long)(((r0 >> 4) + mb) * 48 + (k0 >> 4) + kb) * 128 + w;
        oH[gi] = h;
        oL[gi] = l;
    }
}

// ---------------------------------------------------------------------------
// ctx: L[d][e] = s * sum_c U[h*64+d][c] * Wv[c][h*64+e]  via bf16x3 mma,
// then column-wise softmax (over d) -> g_ctx. grid (12, 32), block 256.
// ---------------------------------------------------------------------------
__global__ __launch_bounds__(256) void ctx_kernel()
{
    __shared__ float Ls[64][68];
    const int z = blockIdx.y;
    const int m = z >> 4, b = z & 15;
    const int h = blockIdx.x;
    const float* U = &g_U[m][b][0] + (long long)(h * 64) * DIMC;
    const uint32_t* Bh = &g_Wvh[m][0];
    const uint32_t* Bl = &g_Wvl[m][0];

    const int tid = threadIdx.x;
    const int wid = tid >> 5, lane = tid & 31;
    const int wm = wid >> 1, wn = wid & 1;
    const int grp = lane >> 2, qid = lane & 3;

    float acc[2][2][4];
#pragma unroll
    for (int a = 0; a < 2; a++)
#pragma unroll
        for (int c = 0; c < 2; c++)
#pragma unroll
            for (int r = 0; r < 4; r++) acc[a][c][r] = 0.f;

    for (int ks = 0; ks < 48; ks++) {
        const float* Ur = U + (long long)(wm * 16 + grp) * DIMC + ks * 16 + 2 * qid;
        float2 p0 = *(const float2*)(Ur);
        float2 p1 = *(const float2*)(Ur + 8 * DIMC);
        float2 p2 = *(const float2*)(Ur + 8);
        float2 p3 = *(const float2*)(Ur + 8 * DIMC + 8);
        uint32_t ah[4], al[4];
        split2_bf16(p0.x, p0.y, ah[0], al[0]);
        split2_bf16(p1.x, p1.y, ah[1], al[1]);
        split2_bf16(p2.x, p2.y, ah[2], al[2]);
        split2_bf16(p3.x, p3.y, ah[3], al[3]);
#pragma unroll
        for (int nb = 0; nb < 2; nb++) {
            const long long gi =
                ((long long)(4 * h + 2 * wn + nb) * 48 + ks) * 128 + lane * 4;
            uint4 bh = *(const uint4*)(Bh + gi);
            uint4 bl = *(const uint4*)(Bl + gi);
            uint32_t bh0[2] = {bh.x, bh.z};
            uint32_t bl0[2] = {bl.x, bl.z};
            uint32_t bh1[2] = {bh.y, bh.w};
            uint32_t bl1[2] = {bl.y, bl.w};
            mma_bf16(acc[nb][0], ah, bh0);
            mma_bf16(acc[nb][0], al, bh0);
            mma_bf16(acc[nb][0], ah, bl0);
            mma_bf16(acc[nb][1], ah, bh1);
            mma_bf16(acc[nb][1], al, bh1);
            mma_bf16(acc[nb][1], ah, bl1);
        }
    }

    const float SCALE = 0.125f;
#pragma unroll
    for (int nb = 0; nb < 2; nb++)
#pragma unroll
        for (int hf = 0; hf < 2; hf++) {
            const int r = wm * 16 + grp;
            const int c = wn * 32 + nb * 16 + hf * 8 + 2 * qid;
            Ls[r][c]         = acc[nb][hf][0] * SCALE;
            Ls[r][c + 1]     = acc[nb][hf][1] * SCALE;
            Ls[r + 8][c]     = acc[nb][hf][2] * SCALE;
            Ls[r + 8][c + 1] = acc[nb][hf][3] * SCALE;
        }
    __syncthreads();

    if (tid < 64) {
        const int e = tid;
        float mx = -1e30f;
#pragma unroll 8
        for (int d = 0; d < 64; d++) mx = fmaxf(mx, Ls[d][e]);
        float s = 0.f;
#pragma unroll 8
        for (int d = 0; d < 64; d++) {
            float v = expf(Ls[d][e] - mx);
            Ls[d][e] = v;
            s += v;
        }
        const float inv = 1.f / s;
        float* cx = &g_ctx[m][b][h][0];
#pragma unroll 8
        for (int d = 0; d < 64; d++) cx[d * 64 + e] = Ls[d][e] * inv;
    }
}

// ---------------------------------------------------------------------------
// out_m[b, n, h*64+e] = sum_d X_m[b, n, h*64+d] * ctx_{1-m}[b][h][d][e]
// ---------------------------------------------------------------------------
__global__ __launch_bounds__(256) void out_kernel(
    const float* __restrict__ rgb, const float* __restrict__ depth,
    float* __restrict__ out)
{
    extern __shared__ char smem[];
    uint32_t* As = (uint32_t*)smem;                 // [128][68]
    uint32_t* Bs = (uint32_t*)smem + 128 * 68;      // [64][68]

    const int z = blockIdx.z;
    const int m = z >> 4, b = z & 15;
    const int h = blockIdx.y;
    const int n0 = blockIdx.x * 128;

    const float* X = (m == 0 ? rgb : depth) + ((long long)b * NTOK + n0) * DIMC + h * HD;
    const float* cx = &g_ctx[1 - m][b][h][0];
    float* O = out + (long long)m * BATCH * NTOK * DIMC + ((long long)b * NTOK + n0) * DIMC + h * HD;

    const int tid = threadIdx.x;
    const int wid = tid >> 5, lane = tid & 31;
    const int wm = wid >> 2, wn = wid & 3;
    const int grp = lane >> 2, qid = lane & 3;

#pragma unroll
    for (int t = 0; t < 8; t++) {
        const int f4 = tid + t * 256;
        const int r = f4 >> 4;
        const int cg = (f4 & 15) << 2;
        float4 v = *(const float4*)(X + (long long)r * DIMC + cg);
        As[r * 68 + cg + 0] = to_tf32(v.x); As[r * 68 + cg + 1] = to_tf32(v.y);
        As[r * 68 + cg + 2] = to_tf32(v.z); As[r * 68 + cg + 3] = to_tf32(v.w);
    }
#pragma unroll
    for (int t = 0; t < 4; t++) {
        const int f4 = tid + t * 256;
        const int d = f4 >> 4;
        const int eg = (f4 & 15) << 2;
        float4 v = *(const float4*)(cx + d * 64 + eg);
        Bs[(eg + 0) * 68 + d] = to_tf32(v.x); Bs[(eg + 1) * 68 + d] = to_tf32(v.y);
        Bs[(eg + 2) * 68 + d] = to_tf32(v.z); Bs[(eg + 3) * 68 + d] = to_tf32(v.w);
    }
    __syncthreads();

    float acc[4][2][4];
#pragma unroll
    for (int a = 0; a < 4; a++)
#pragma unroll
        for (int c = 0; c < 2; c++)
#pragma unroll
            for (int r = 0; r < 4; r++) acc[a][c][r] = 0.f;

#pragma unroll
    for (int ks = 0; ks < 8; ks++) {
        const int kq = (ks << 3) + qid;
        uint32_t ah[4][4], bh[2][2];
#pragma unroll
        for (int mi = 0; mi < 4; mi++) {
            const int i = wm * 64 + mi * 16 + grp;
            ah[mi][0] = As[i * 68 + kq];           ah[mi][1] = As[(i + 8) * 68 + kq];
            ah[mi][2] = As[i * 68 + kq + 4];       ah[mi][3] = As[(i + 8) * 68 + kq + 4];
        }
#pragma unroll
        for (int nj = 0; nj < 2; nj++) {
            const int n = wn * 16 + nj * 8 + grp;
            bh[nj][0] = Bs[n * 68 + kq]; bh[nj][1] = Bs[n * 68 + kq + 4];
        }
#pragma unroll
        for (int mi = 0; mi < 4; mi++)
#pragma unroll
            for (int nj = 0; nj < 2; nj++)
                mma_tf32(acc[mi][nj], ah[mi], bh[nj]);
    }

#pragma unroll
    for (int mi = 0; mi < 4; mi++) {
        const int r0 = wm * 64 + mi * 16 + grp;
#pragma unroll
        for (int nj = 0; nj < 2; nj++) {
            const int c0c = wn * 16 + nj * 8 + 2 * qid;
            *(float2*)(O + (long long)r0 * DIMC + c0c) =
                make_float2(acc[mi][nj][0], acc[mi][nj][1]);
            *(float2*)(O + (long long)(r0 + 8) * DIMC + c0c) =
                make_float2(acc[mi][nj][2], acc[mi][nj][3]);
        }
    }
}

// ---------------------------------------------------------------------------
extern "C" void kernel_launch(void* const* d_in, const int* in_sizes, int n_in,
                              void* d_out, int out_size)
{
    const float* rgb = (const float*)d_in[0];
    const float* dep = (const float*)d_in[1];
    const float* Wr  = (const float*)d_in[2];
    const float* Wd  = (const float*)d_in[3];
    float* out = (float*)d_out;

    uint32_t *pXh, *pXl, *pWh, *pWl, *pWvh, *pWvl;
    float *pGf, *pU;
    cudaGetSymbolAddress((void**)&pXh, g_Xh);
    cudaGetSymbolAddress((void**)&pXl, g_Xl);
    cudaGetSymbolAddress((void**)&pWh, g_Wh);
    cudaGetSymbolAddress((void**)&pWl, g_Wl);
    cudaGetSymbolAddress((void**)&pWvh, g_Wvh);
    cudaGetSymbolAddress((void**)&pWvl, g_Wvl);
    cudaGetSymbolAddress((void**)&pGf, g_Gf);
    cudaGetSymbolAddress((void**)&pU, g_U);

    uint32_t *pGh, *pGl;
    cudaGetSymbolAddress((void**)&pGh, g_Gh);
    cudaGetSymbolAddress((void**)&pGl, g_Gl);

    cudaFuncSetAttribute(gemm_bf16_kernel,
                         cudaFuncAttributeMaxDynamicSharedMemorySize, GEMM_SMEM);
    cudaFuncSetAttribute(out_kernel,
                         cudaFuncAttributeMaxDynamicSharedMemorySize, OUT_SMEM);

    const long long XS = (long long)NTOK * DIMC;

    // pack X (both modalities), Wk, Wv
    pack_bf16_kernel<<<dim3(12, 64, 32), 256>>>(rgb, dep, XS, DIMC, NTOK, 16,
                                                pXh, pXl, XPB);
    pack_bf16_kernel<<<dim3(12, 12, 2), 256>>>(Wr, Wd, 0, 2 * DIMC, DIMC, 1,
                                               pWh, pWl, WPB);
    pack_bf16_kernel<<<dim3(12, 12, 2), 256>>>(Wr + DIMC, Wd + DIMC, 0, 2 * DIMC,
                                               DIMC, 1, pWvh, pWvl, WPB);

    // G = XᵀX: split-K=2, triangular tiles, f32 plane stores
    // blockIdx.x = tile*2 + ks; plane stride = 32 * GFB
    gemm_bf16_kernel<<<dim3(42, 32), 128, GEMM_SMEM>>>(
        pXh, pXl, XPB, 1, pXh, pXl, XPB,
        NTOK / 16, 64, 2, 1, pGf, GFB, 32 * GFB);

    // packG: plane sum + symmetric expansion + bf16 fragment pack
    packG_kernel<<<dim3(144, 32), 128>>>();

    // U = Wkᵀ G
    gemm_bf16_kernel<<<dim3(36, 32), 128, GEMM_SMEM>>>(
        pWh, pWl, WPB, 16, pGh, pGl, GPB,
        48, 24, 1, 0, pU, UBE, 0);

    // ctx: bf16x3 mma logits + softmax
    ctx_kernel<<<dim3(NHEADS, 32), 256>>>();

    // out = X @ blockdiag(ctx_other)
    out_kernel<<<dim3(NTOK / 128, NHEADS, 32), 256, OUT_SMEM>>>(rgb, dep, out);
}